// round 8
// baseline (speedup 1.0000x reference)
#include <cuda_runtime.h>
#include <cuda_bf16.h>
#include <cstdint>

#define B_  4
#define C_  256
#define CK_ 32
#define N_  4096
#define LOG2E 1.4426950408889634f

// Scratch (allocation-free): projections.
__device__ float g_f[B_ * N_ * CK_];                    // [b][n][k] f, pre-scaled by log2e
__device__ __nv_bfloat16 g_ghi[B_ * N_ * CK_];          // [b][n][k] key hi
__device__ __nv_bfloat16 g_glo[B_ * N_ * CK_];          // [b][n][k] key lo
__device__ __nv_bfloat16 g_vhi[(size_t)B_ * C_ * N_];   // [b][d][n] value hi
__device__ __nv_bfloat16 g_vlo[(size_t)B_ * C_ * N_];   // [b][d][n] value lo

// ---------------------------------------------------------------------------
// helpers
// ---------------------------------------------------------------------------
__device__ __forceinline__ uint32_t smem_u32(const void* p) {
    uint32_t a;
    asm("{ .reg .u64 t; cvta.to.shared.u64 t, %1; cvt.u32.u64 %0, t; }"
        : "=r"(a) : "l"(p));
    return a;
}
__device__ __forceinline__ uint32_t pack_bf16x2(float up, float lo) {
    uint32_t r;
    asm("cvt.rn.bf16x2.f32 %0, %1, %2;" : "=r"(r) : "f"(up), "f"(lo));
    return r;
}
__device__ __forceinline__ void split_pair(float x0, float x1,
                                           uint32_t& h, uint32_t& lo) {
    h = pack_bf16x2(x1, x0);
    float h0 = __uint_as_float(h << 16);
    float h1 = __uint_as_float(h & 0xFFFF0000u);
    lo = pack_bf16x2(x1 - h1, x0 - h0);
}
// fast 2^y, FMA-pipe only
__device__ __forceinline__ float fexp2(float y) {
    y = fmaxf(y, -80.f);
    float fk = y + 12582912.0f;
    int ik = __float_as_int(fk);
    float r = y - (fk - 12582912.0f);
    int e = (ik + (127 - 0x4B400000)) << 23;
    float p = 0.0013333558f;
    p = fmaf(p, r, 0.009618129f);
    p = fmaf(p, r, 0.055504109f);
    p = fmaf(p, r, 0.240226507f);
    p = fmaf(p, r, 0.693147181f);
    p = fmaf(p, r, 1.0f);
    return __int_as_float(e) * p;
}

__device__ __forceinline__ void ldsm_x4(uint32_t* r, uint32_t addr) {
    asm volatile("ldmatrix.sync.aligned.m8n8.x4.shared.b16 {%0,%1,%2,%3}, [%4];"
        : "=r"(r[0]), "=r"(r[1]), "=r"(r[2]), "=r"(r[3]) : "r"(addr));
}
__device__ __forceinline__ void mma16816(float* d, const uint32_t* a,
                                         const uint32_t* b) {
    asm volatile(
        "mma.sync.aligned.m16n8k16.row.col.f32.bf16.bf16.f32 "
        "{%0,%1,%2,%3}, {%4,%5,%6,%7}, {%8,%9}, {%0,%1,%2,%3};"
        : "+f"(d[0]), "+f"(d[1]), "+f"(d[2]), "+f"(d[3])
        : "r"(a[0]), "r"(a[1]), "r"(a[2]), "r"(a[3]), "r"(b[0]), "r"(b[1]));
}
__device__ __forceinline__ void cp16(uint32_t dst, const void* src) {
    asm volatile("cp.async.cg.shared.global [%0], [%1], 16;"
                 :: "r"(dst), "l"(src) : "memory");
}
#define CP_COMMIT() asm volatile("cp.async.commit_group;" ::: "memory")
#define CP_WAIT0()  asm volatile("cp.async.wait_group 0;" ::: "memory")
#define STS32(addr, v) \
    asm volatile("st.shared.b32 [%0], %1;" :: "r"(addr), "r"(v) : "memory")

// ---------------------------------------------------------------------------
// Projection: OUT[r][n] = sum_c W[r][c]*x[b][c][n], W = stack(w1,w2,w3).
// Tile 64r x 256n, 256 threads, micro 8x8, W transposed in smem (float4 both).
// ---------------------------------------------------------------------------
__device__ __forceinline__ float wval(const float* __restrict__ w1,
                                      const float* __restrict__ w2,
                                      const float* __restrict__ w3,
                                      int r, int c) {
    if (r < 32)  return w1[r * C_ + c];
    if (r < 64)  return w2[(r - 32) * C_ + c];
    return w3[(r - 64) * C_ + c];
}

__global__ __launch_bounds__(256)
void proj_kernel(const float* __restrict__ x,
                 const float* __restrict__ w1,
                 const float* __restrict__ w2,
                 const float* __restrict__ w3) {
    __shared__ float Wt[16][72];    // [c][r]  transposed W chunk
    __shared__ float Xt[16][260];   // [c][n]

    const int b  = blockIdx.z;
    const int R0 = blockIdx.y * 64;
    const int N0 = blockIdx.x * 256;
    const int t  = threadIdx.x;
    const int tx = t & 31, ty = t >> 5;   // cols tx*8, rows ty*8
    const float* xb = x + (size_t)b * C_ * N_;

    float acc[8][8];
    #pragma unroll
    for (int i = 0; i < 8; i++)
        #pragma unroll
        for (int j = 0; j < 8; j++) acc[i][j] = 0.f;

    for (int kc = 0; kc < C_; kc += 16) {
        __syncthreads();
        {   // W fill (coalesced read, transposed store)
            int r = t >> 2, c4 = (t & 3) * 4;
            #pragma unroll
            for (int i = 0; i < 4; i++)
                Wt[c4 + i][r] = wval(w1, w2, w3, R0 + r, kc + c4 + i);
        }
        {   // X fill (float4)
            int c = t >> 4, nb = (t & 15) * 16;
            #pragma unroll
            for (int j = 0; j < 4; j++)
                *(float4*)&Xt[c][nb + 4 * j] =
                    *(const float4*)(xb + (size_t)(kc + c) * N_ + N0 + nb + 4 * j);
        }
        __syncthreads();
        #pragma unroll
        for (int cc = 0; cc < 16; cc++) {
            float4 wa = *(const float4*)&Wt[cc][ty * 8];
            float4 wb = *(const float4*)&Wt[cc][ty * 8 + 4];
            float4 xa = *(const float4*)&Xt[cc][tx * 8];
            float4 xc = *(const float4*)&Xt[cc][tx * 8 + 4];
            float w8[8] = {wa.x, wa.y, wa.z, wa.w, wb.x, wb.y, wb.z, wb.w};
            float x8[8] = {xa.x, xa.y, xa.z, xa.w, xc.x, xc.y, xc.z, xc.w};
            #pragma unroll
            for (int i = 0; i < 8; i++)
                #pragma unroll
                for (int j = 0; j < 8; j++) acc[i][j] += w8[i] * x8[j];
        }
    }

    #pragma unroll
    for (int i = 0; i < 8; i++) {
        int r = R0 + ty * 8 + i;
        #pragma unroll
        for (int j = 0; j < 8; j++) {
            int n = N0 + tx * 8 + j;
            float v = acc[i][j];
            if (r < 32) {
                g_f[((size_t)b * N_ + n) * CK_ + r] = v * LOG2E;
            } else if (r < 64) {
                __nv_bfloat16 hi = __float2bfloat16(v);
                __nv_bfloat16 lo = __float2bfloat16(v - __bfloat162float(hi));
                size_t o = ((size_t)b * N_ + n) * CK_ + (r - 32);
                g_ghi[o] = hi; g_glo[o] = lo;
            } else {
                __nv_bfloat16 hi = __float2bfloat16(v);
                __nv_bfloat16 lo = __float2bfloat16(v - __bfloat162float(hi));
                size_t o = ((size_t)b * C_ + (r - 64)) * N_ + n;
                g_vhi[o] = hi; g_vlo[o] = lo;
            }
        }
    }
}

// ---------------------------------------------------------------------------
// Attention: 64 query rows/CTA, 32-key tiles, 2 CTAs/SM for phase overlap.
// 8 warps: warp = (band = w&3 -> m16, nsl = w>>2 -> S key-half / O d-half).
// Prefetch for kt+1 is issued AFTER the mid sync (all warps past O(kt-1)),
// so cp.async never overwrites a buffer still being read.  (R7 race fix)
// ---------------------------------------------------------------------------
#define GPitch 80
#define SM_G   0
#define GBUF   5120          // per buffer (hi 32x80 + lo 32x80)
#define G_LO   2560
#define SM_V   10240
#define VBUF   40960         // per buffer (hi 256x80 + lo)
#define V_LO   20480
#define SM_P   92160         // P hi [64][80], then lo
#define P_LO   5120
#define SM_L   102400        // 64 floats
#define ATTN_SMEM 102656

__device__ __forceinline__ void cp_tile(uint32_t sb, int buf, int b, int m0, int t) {
    const __nv_bfloat16* gh = g_ghi + (size_t)b * N_ * CK_;
    const __nv_bfloat16* gl = g_glo + (size_t)b * N_ * CK_;
    const __nv_bfloat16* vh = g_vhi + (size_t)b * C_ * N_;
    const __nv_bfloat16* vl = g_vlo + (size_t)b * C_ * N_;

    // g tile: 32 rows x 64B payload, hi (t<128) / lo (t>=128)
    {
        int row = (t >> 2) & 31, q = t & 3;
        uint32_t gd = sb + SM_G + buf * GBUF + (t < 128 ? 0 : G_LO) + row * GPitch + q * 16;
        const __nv_bfloat16* s = (t < 128 ? gh : gl) + (size_t)(m0 + row) * CK_ + q * 8;
        cp16(gd, s);
    }
    // V tile: 256 rows x 64B payload, hi (i<4) / lo (i>=4)
    #pragma unroll
    for (int i = 0; i < 8; i++) {
        int idx = i * 256 + t;
        int d = (idx >> 2) & 255, q = idx & 3;
        uint32_t vd = sb + SM_V + buf * VBUF + (i < 4 ? 0 : V_LO) + d * GPitch + q * 16;
        const __nv_bfloat16* s = (i < 4 ? vh : vl) + (size_t)d * N_ + m0 + q * 8;
        cp16(vd, s);
    }
}

__global__ __launch_bounds__(256, 2)
void attn_kernel(const float* __restrict__ x, float* __restrict__ out) {
    extern __shared__ char smem[];
    const uint32_t sb = smem_u32(smem);
    float* Ls = (float*)(smem + SM_L);

    const int b  = blockIdx.y;
    const int n0 = blockIdx.x * 64;
    const int t  = threadIdx.x;
    const int w  = t >> 5, l = t & 31;
    const int g  = l >> 2, tq = l & 3;
    const int band = w & 3;     // m16 band
    const int nsl  = w >> 2;    // 0/1: S key-half, O d-half

    // ---- persistent f fragments: rows n0 + band*16 ----
    uint32_t fah[2][4], fal[2][4];
    {
        const float* fb = g_f + (size_t)b * N_ * CK_;
        int r0 = n0 + band * 16 + g;
        #pragma unroll
        for (int ks = 0; ks < 2; ks++) {
            int cb = ks * 16 + 2 * tq;
            float2 p00 = *(const float2*)(fb + (size_t)r0 * CK_ + cb);
            float2 p10 = *(const float2*)(fb + (size_t)(r0 + 8) * CK_ + cb);
            float2 p01 = *(const float2*)(fb + (size_t)r0 * CK_ + cb + 8);
            float2 p11 = *(const float2*)(fb + (size_t)(r0 + 8) * CK_ + cb + 8);
            split_pair(p00.x, p00.y, fah[ks][0], fal[ks][0]);
            split_pair(p10.x, p10.y, fah[ks][1], fal[ks][1]);
            split_pair(p01.x, p01.y, fah[ks][2], fal[ks][2]);
            split_pair(p11.x, p11.y, fah[ks][3], fal[ks][3]);
        }
    }
    if (t < 64) Ls[t] = 0.f;

    float o[16][4];
    #pragma unroll
    for (int j = 0; j < 16; j++)
        #pragma unroll
        for (int i = 0; i < 4; i++) o[j][i] = 0.f;
    float Lacc0 = 0.f, Lacc1 = 0.f;

    // invariant addresses
    const uint32_t gB_off = (uint32_t)((nsl * 16 + (l & 7) + ((l >> 4) & 1) * 8) * GPitch
                                       + ((l >> 3) & 1) * 16);
    const uint32_t pSt = sb + SM_P + (uint32_t)((band * 16 + g) * GPitch + nsl * 32 + tq * 4);
    const uint32_t pA_off = sb + SM_P + (uint32_t)((band * 16 + (l & 15)) * GPitch
                                                   + ((l >> 4) & 1) * 16);
    const uint32_t vB_off = (uint32_t)((nsl * 128 + (l & 7) + ((l >> 4) & 1) * 8) * GPitch
                                       + ((l >> 3) & 1) * 16);

    cp_tile(sb, 0, b, 0, t);
    CP_COMMIT();

    for (int kt = 0; kt < 128; kt++) {
        CP_WAIT0();        // buffer kt&1 fully landed
        __syncthreads();   // all warps done with O(kt-1); tile data visible

        // -------- S = f @ g^T (m16 x n16 x k32, 3 terms) --------
        const uint32_t gbase = sb + SM_G + (kt & 1) * GBUF;
        float sd[2][4];
        #pragma unroll
        for (int nt = 0; nt < 2; nt++)
            #pragma unroll
            for (int i = 0; i < 4; i++) sd[nt][i] = 0.f;

        #pragma unroll
        for (int ks = 0; ks < 2; ks++) {
            uint32_t gh4[4], gl4[4];
            ldsm_x4(gh4, gbase + ks * 32 + gB_off);
            ldsm_x4(gl4, gbase + G_LO + ks * 32 + gB_off);
            mma16816(sd[0], fah[ks], gh4);
            mma16816(sd[1], fah[ks], gh4 + 2);
            mma16816(sd[0], fah[ks], gl4);
            mma16816(sd[1], fah[ks], gl4 + 2);
            mma16816(sd[0], fal[ks], gh4);
            mma16816(sd[1], fal[ks], gh4 + 2);
        }

        // -------- p = 2^s, register L, P -> smem --------
        #pragma unroll
        for (int nt = 0; nt < 2; nt++) {
            float p0 = fexp2(sd[nt][0]);
            float p1 = fexp2(sd[nt][1]);
            float p2 = fexp2(sd[nt][2]);
            float p3 = fexp2(sd[nt][3]);
            Lacc0 += p0 + p1; Lacc1 += p2 + p3;
            uint32_t h01, l01, h23, l23;
            split_pair(p0, p1, h01, l01);
            split_pair(p2, p3, h23, l23);
            uint32_t pa = pSt + nt * 16;
            STS32(pa, h01);                    STS32(pa + P_LO, l01);
            STS32(pa + 8 * GPitch, h23);       STS32(pa + 8 * GPitch + P_LO, l23);
        }
        __syncthreads();   // P visible; all warps past O(kt-1) reads of old buffer

        // safe point: issue prefetch of kt+1 (overwrites buffer (kt+1)&1,
        // whose last readers finished before this iteration's first sync)
        if (kt < 127) {
            cp_tile(sb, (kt + 1) & 1, b, (kt + 1) * 32, t);
            CP_COMMIT();
        }

        // -------- O += P @ V (m16 x n128 x k32, 3 terms) --------
        const uint32_t vbase = sb + SM_V + (kt & 1) * VBUF;
        #pragma unroll
        for (int ks = 0; ks < 2; ks++) {
            uint32_t ah[4], al[4];
            ldsm_x4(ah, pA_off + ks * 32);
            ldsm_x4(al, pA_off + P_LO + ks * 32);
            #pragma unroll
            for (int np = 0; np < 8; np++) {
                uint32_t ba = vbase + np * (16 * GPitch) + ks * 32 + vB_off;
                uint32_t bh[4], bl[4];
                ldsm_x4(bh, ba);
                ldsm_x4(bl, ba + V_LO);
                mma16816(o[2 * np],     ah, bh);
                mma16816(o[2 * np + 1], ah, bh + 2);
                mma16816(o[2 * np],     ah, bl);
                mma16816(o[2 * np + 1], ah, bl + 2);
                mma16816(o[2 * np],     al, bh);
                mma16816(o[2 * np + 1], al, bh + 2);
            }
        }
    }

    // -------- finalize L --------
    Lacc0 += __shfl_xor_sync(0xFFFFFFFFu, Lacc0, 1);
    Lacc0 += __shfl_xor_sync(0xFFFFFFFFu, Lacc0, 2);
    Lacc1 += __shfl_xor_sync(0xFFFFFFFFu, Lacc1, 1);
    Lacc1 += __shfl_xor_sync(0xFFFFFFFFu, Lacc1, 2);
    __syncthreads();   // O-mma of last tile done everywhere; Ls zero-init long since visible
    if (tq == 0) {
        atomicAdd(&Ls[band * 16 + g], Lacc0);
        atomicAdd(&Ls[band * 16 + g + 8], Lacc1);
    }
    __syncthreads();

    // -------- epilogue: out[b][d][n] = O/L + x --------
    {
        int row = band * 16 + g;
        float li0 = 1.0f / Ls[row];
        float li1 = 1.0f / Ls[row + 8];
        #pragma unroll
        for (int j = 0; j < 16; j++) {
            int d = nsl * 128 + j * 8 + 2 * tq;
            size_t base = ((size_t)b * C_ + d) * N_ + n0 + row;
            out[base]          = o[j][0] * li0 + x[base];
            out[base + N_]     = o[j][1] * li0 + x[base + N_];
            out[base + 8]      = o[j][2] * li1 + x[base + 8];
            out[base + N_ + 8] = o[j][3] * li1 + x[base + N_ + 8];
        }
    }
}

// ---------------------------------------------------------------------------
extern "C" void kernel_launch(void* const* d_in, const int* in_sizes, int n_in,
                              void* d_out, int out_size) {
    const float* x  = (const float*)d_in[0];
    const float* w1 = (const float*)d_in[1];
    const float* w2 = (const float*)d_in[2];
    const float* w3 = (const float*)d_in[3];
    float* out = (float*)d_out;

    cudaFuncSetAttribute(attn_kernel,
                         cudaFuncAttributeMaxDynamicSharedMemorySize, ATTN_SMEM);

    dim3 pg(N_ / 256, 5, B_);         // 16 n-tiles x 5 r-tiles x 4 batches
    proj_kernel<<<pg, 256>>>(x, w1, w2, w3);

    dim3 ag(N_ / 64, B_);             // 64 q-tiles x 4 batches
    attn_kernel<<<ag, 256, ATTN_SMEM>>>(x, out);
}